// round 15
// baseline (speedup 1.0000x reference)
#include <cuda_runtime.h>

// GRU_67714454389230: 2-layer GRU (H=12, IN=18) + fc(12->1), B=4096, T=512.
// Round 15: SINGLE kernel, block-role specialization to overlap gi0 with the
// scan (the 2-kernel split serializes them via the capture graph edge).
//   blocks [0, 16384)      : producers — 128 gi-rows each -> R7 float4-plane
//   blocks [16384, 17408)  : consumers — exact R7 scan (measured best 320.7us)
// Sync: g_cnt[W] counters (release atomicAdd after threadfence; acquire spin +
// nanosleep). Deadlock-free by capacity: launch_bounds(32,9) -> >=1332
// resident blocks > 1024 scan blocks, so producers always have slots.
// Counters reset by the scan block at exit -> deterministic graph replays.

static constexpr int IN_DIM = 18;
static constexpr int HID    = 12;
static constexpr int BATCH  = 4096;
static constexpr int SEQ    = 512;
static constexpr size_t NROWS = (size_t)BATCH * SEQ;   // 2,097,152

static constexpr int PROD_BLOCKS = (int)(NROWS / 128);  // 16384
static constexpr int SCAN_BLOCKS = BATCH / 4;           // 1024
static constexpr int GRID        = PROD_BLOCKS + SCAN_BLOCKS;

typedef unsigned long long ull;

// plane layout: g_gi0[u*NROWS + (b*SEQ+t)] = float4(gi_r, gi_z, gi_n, 0)
__device__ float4 g_gi0[HID * NROWS];
// one counter per scan block; producers 16W..16W+15 feed scan block W
__device__ unsigned g_cnt[SCAN_BLOCKS];   // zero-initialized

// ---------------- helpers ----------------
__device__ __forceinline__ ull ffma2(ull a, ull b, ull c) {
    ull d;
    asm("fma.rn.f32x2 %0, %1, %2, %3;" : "=l"(d) : "l"(a), "l"(b), "l"(c));
    return d;
}
__device__ __forceinline__ float f2sum(ull v) {
    float lo, hi;
    asm("mov.b64 {%0, %1}, %2;" : "=f"(lo), "=f"(hi) : "l"(v));
    return lo + hi;
}
__device__ __forceinline__ ull fpack(float lo, float hi) {
    ull v;
    asm("mov.b64 %0, {%1, %2};" : "=l"(v) : "f"(lo), "f"(hi));
    return v;
}
__device__ __forceinline__ float tanhapx(float x) {
    float y;
    asm("tanh.approx.f32 %0, %1;" : "=f"(y) : "f"(x));
    return y;
}
__device__ __forceinline__ float fast_sig(float x) {
    return fmaf(tanhapx(0.5f * x), 0.5f, 0.5f);
}

__global__ __launch_bounds__(32, 9)
void gru_overlap_kernel(const float* __restrict__ x,
                        const float* __restrict__ w_ih0, const float* __restrict__ b_ih0,
                        const float* __restrict__ w_hh0, const float* __restrict__ b_hh0,
                        const float* __restrict__ w_ih1, const float* __restrict__ w_hh1,
                        const float* __restrict__ b_ih1, const float* __restrict__ b_hh1,
                        const float* __restrict__ fc_w, const float* __restrict__ fc_b,
                        float* __restrict__ out)
{
    __shared__ ull   s_w[36][9];
    __shared__ float s_b[36];
    __shared__ __align__(16) float s_h1[2][2][HID];
    __shared__ __align__(16) float s_h2[2][2][HID];

    const int lane = threadIdx.x;

    if (blockIdx.x < PROD_BLOCKS) {
        // ================= producer: 128 rows of gi0 =================
        for (int i = lane; i < 36 * 9; i += 32) {
            const int j = i / 9, k = i % 9;
            s_w[j][k] = *(const ull*)(w_ih0 + j * IN_DIM + 2 * k);
        }
        for (int i = lane; i < 36; i += 32) s_b[i] = b_ih0[i];
        __syncwarp();

        const size_t row0 = (size_t)blockIdx.x * 128;
        // lane handles rows lane + 32j (j = 0..3)
        ull xv[4][9];
#pragma unroll
        for (int j = 0; j < 4; ++j) {
            const float* xr = x + (row0 + lane + 32 * j) * IN_DIM;
#pragma unroll
            for (int k = 0; k < 9; ++k) xv[j][k] = *(const ull*)(xr + 2 * k);
        }

#pragma unroll
        for (int u = 0; u < HID; ++u) {
            float res[4][3];
#pragma unroll
            for (int g = 0; g < 3; ++g) {
                const int jrow = g * HID + u;
                ull w[9];
#pragma unroll
                for (int k = 0; k < 9; ++k) w[k] = s_w[jrow][k];
                const float b = s_b[jrow];
#pragma unroll
                for (int j = 0; j < 4; ++j) {
                    ull acc = fpack(b, 0.0f);
#pragma unroll
                    for (int k = 0; k < 9; ++k) acc = ffma2(xv[j][k], w[k], acc);
                    res[j][g] = f2sum(acc);
                }
            }
            float4* plane = g_gi0 + (size_t)u * NROWS + row0;
#pragma unroll
            for (int j = 0; j < 4; ++j)
                plane[lane + 32 * j] = make_float4(res[j][0], res[j][1], res[j][2], 0.0f);
        }

        __threadfence();     // order this lane's gi writes before the count
        __syncwarp();
        if (lane == 0) atomicAdd(&g_cnt[blockIdx.x >> 4], 1u);
        return;
    }

    // ================= consumer: exact R7 scan for 4 batches =================
    const int W     = blockIdx.x - PROD_BLOCKS;
    const int grp_l = lane >> 4;
    const int sub   = lane & 15;
    const int u     = (sub < HID) ? sub : HID - 1;
    const int bA    = 4 * W + 2 * grp_l;
    const int bB    = bA + 1;

    // All recurrent weights in registers (f32x2 pairs) — load while waiting.
    ull whh0[3][6], wih1[3][6], whh1[3][6];
#pragma unroll
    for (int g = 0; g < 3; ++g) {
        const ull* p0 = (const ull*)(w_hh0 + (g * HID + u) * HID);
        const ull* p1 = (const ull*)(w_ih1 + (g * HID + u) * HID);
        const ull* p2 = (const ull*)(w_hh1 + (g * HID + u) * HID);
#pragma unroll
        for (int i = 0; i < 6; ++i) {
            whh0[g][i] = p0[i]; wih1[g][i] = p1[i]; whh1[g][i] = p2[i];
        }
    }

    const float bh0r = b_hh0[u];
    const float bh0z = b_hh0[HID + u];
    const ull pbh0n = fpack(b_hh0[2 * HID + u], 0.0f);
    const ull pb2r  = fpack(b_ih1[u]           + b_hh1[u],          0.0f);
    const ull pb2z  = fpack(b_ih1[HID + u]     + b_hh1[HID + u],    0.0f);
    const ull pb2in = fpack(b_ih1[2 * HID + u], 0.0f);
    const ull pb2hn = fpack(b_hh1[2 * HID + u], 0.0f);
    const float fcb = fc_b[0];
    ull fcwp[6];
#pragma unroll
    for (int i = 0; i < 6; ++i) fcwp[i] = *(const ull*)(fc_w + 2 * i);

    // wait for the 16 producer blocks feeding this scan block
    if (lane == 0) {
        unsigned v;
        do {
            asm volatile("ld.acquire.gpu.b32 %0, [%1];"
                         : "=r"(v) : "l"(&g_cnt[W]) : "memory");
            if (v < 16u) __nanosleep(128);
        } while (v < 16u);
    }
    __syncthreads();

    ull h1A[6], h1B[6], h2A[6], h2B[6];
#pragma unroll
    for (int i = 0; i < 6; ++i) { h1A[i] = h1B[i] = h2A[i] = h2B[i] = 0ull; }
    float hp1A = 0.0f, hp1B = 0.0f, hp2A = 0.0f, hp2B = 0.0f;

    const float4* gpA = g_gi0 + (size_t)u * NROWS + (size_t)bA * SEQ;
    const float4* gpB = g_gi0 + (size_t)u * NROWS + (size_t)bB * SEQ;

    float4 gcA = gpA[0];
    float4 gcB = gpB[0];

#pragma unroll 1
    for (int t = 0; t < SEQ; ++t) {
        const int tn = (t + 1 < SEQ) ? (t + 1) : t;
        const float4 gnA = gpA[tn];
        const float4 gnB = gpB[tn];

        // ---- layer-2 hh dots from PREVIOUS h2 ----
        ull prA = pb2r, pzA = pb2z, pnA = pb2hn;
        ull prB = pb2r, pzB = pb2z, pnB = pb2hn;
#pragma unroll
        for (int i = 0; i < 6; ++i) {
            prA = ffma2(h2A[i], whh1[0][i], prA); prB = ffma2(h2B[i], whh1[0][i], prB);
            pzA = ffma2(h2A[i], whh1[1][i], pzA); pzB = ffma2(h2B[i], whh1[1][i], pzB);
            pnA = ffma2(h2A[i], whh1[2][i], pnA); pnB = ffma2(h2B[i], whh1[2][i], pnB);
        }
        const float a2hnA = f2sum(pnA);
        const float a2hnB = f2sum(pnB);

        // ---- layer 1 ----
        ull qrA = fpack(gcA.x, bh0r), qzA = fpack(gcA.y, bh0z), qnA = pbh0n;
        ull qrB = fpack(gcB.x, bh0r), qzB = fpack(gcB.y, bh0z), qnB = pbh0n;
#pragma unroll
        for (int i = 0; i < 6; ++i) {
            qrA = ffma2(h1A[i], whh0[0][i], qrA); qrB = ffma2(h1B[i], whh0[0][i], qrB);
            qzA = ffma2(h1A[i], whh0[1][i], qzA); qzB = ffma2(h1B[i], whh0[1][i], qzB);
            qnA = ffma2(h1A[i], whh0[2][i], qnA); qnB = ffma2(h1B[i], whh0[2][i], qnB);
        }
        const float r1A = fast_sig(f2sum(qrA));
        const float r1B = fast_sig(f2sum(qrB));
        const float z1A = fast_sig(f2sum(qzA));
        const float z1B = fast_sig(f2sum(qzB));
        const float n1A = tanhapx(fmaf(r1A, f2sum(qnA), gcA.z));
        const float n1B = tanhapx(fmaf(r1B, f2sum(qnB), gcB.z));
        const float hn1A = fmaf(z1A, hp1A - n1A, n1A);
        const float hn1B = fmaf(z1B, hp1B - n1B, n1B);
        hp1A = hn1A; hp1B = hn1B;

        if (sub < HID) { s_h1[grp_l][0][u] = hn1A; s_h1[grp_l][1][u] = hn1B; }
        __syncwarp();
        {
            const ulonglong2* pa = (const ulonglong2*)s_h1[grp_l][0];
            const ulonglong2* pb = (const ulonglong2*)s_h1[grp_l][1];
            const ulonglong2 a0 = pa[0], a1 = pa[1], a2 = pa[2];
            const ulonglong2 b0 = pb[0], b1 = pb[1], b2 = pb[2];
            h1A[0] = a0.x; h1A[1] = a0.y; h1A[2] = a1.x;
            h1A[3] = a1.y; h1A[4] = a2.x; h1A[5] = a2.y;
            h1B[0] = b0.x; h1B[1] = b0.y; h1B[2] = b1.x;
            h1B[3] = b1.y; h1B[4] = b2.x; h1B[5] = b2.y;
        }

        // ---- layer-2 ih dots on fresh h1 ----
        ull piA = pb2in, piB = pb2in;
#pragma unroll
        for (int i = 0; i < 6; ++i) {
            prA = ffma2(h1A[i], wih1[0][i], prA); prB = ffma2(h1B[i], wih1[0][i], prB);
            pzA = ffma2(h1A[i], wih1[1][i], pzA); pzB = ffma2(h1B[i], wih1[1][i], pzB);
            piA = ffma2(h1A[i], wih1[2][i], piA); piB = ffma2(h1B[i], wih1[2][i], piB);
        }
        const float r2A = fast_sig(f2sum(prA));
        const float r2B = fast_sig(f2sum(prB));
        const float z2A = fast_sig(f2sum(pzA));
        const float z2B = fast_sig(f2sum(pzB));
        const float n2A = tanhapx(fmaf(r2A, a2hnA, f2sum(piA)));
        const float n2B = tanhapx(fmaf(r2B, a2hnB, f2sum(piB)));
        const float hn2A = fmaf(z2A, hp2A - n2A, n2A);
        const float hn2B = fmaf(z2B, hp2B - n2B, n2B);
        hp2A = hn2A; hp2B = hn2B;

        if (sub < HID) { s_h2[grp_l][0][u] = hn2A; s_h2[grp_l][1][u] = hn2B; }
        __syncwarp();
        {
            const ulonglong2* pa = (const ulonglong2*)s_h2[grp_l][0];
            const ulonglong2* pb = (const ulonglong2*)s_h2[grp_l][1];
            const ulonglong2 a0 = pa[0], a1 = pa[1], a2 = pa[2];
            const ulonglong2 b0 = pb[0], b1 = pb[1], b2 = pb[2];
            h2A[0] = a0.x; h2A[1] = a0.y; h2A[2] = a1.x;
            h2A[3] = a1.y; h2A[4] = a2.x; h2A[5] = a2.y;
            h2B[0] = b0.x; h2B[1] = b0.y; h2B[2] = b1.x;
            h2B[3] = b1.y; h2B[4] = b2.x; h2B[5] = b2.y;
        }

        // ---- fc on idle lanes 12 (batch A) / 13 (batch B) ----
        if (sub == 12 || sub == 13) {
            const ull* hh = (sub == 12) ? h2A : h2B;
            ull acc = fpack(fcb, 0.0f);
#pragma unroll
            for (int i = 0; i < 6; ++i) acc = ffma2(hh[i], fcwp[i], acc);
            out[(size_t)((sub == 12) ? bA : bB) * SEQ + t] = f2sum(acc);
        }

        gcA = gnA; gcB = gnB;
    }

    // reset counter for the next graph replay
    __syncthreads();
    if (lane == 0) g_cnt[W] = 0u;
}

extern "C" void kernel_launch(void* const* d_in, const int* in_sizes, int n_in,
                              void* d_out, int out_size) {
    const float* x     = (const float*)d_in[0];
    const float* w_ih0 = (const float*)d_in[1];
    const float* w_hh0 = (const float*)d_in[2];
    const float* b_ih0 = (const float*)d_in[3];
    const float* b_hh0 = (const float*)d_in[4];
    const float* w_ih1 = (const float*)d_in[5];
    const float* w_hh1 = (const float*)d_in[6];
    const float* b_ih1 = (const float*)d_in[7];
    const float* b_hh1 = (const float*)d_in[8];
    const float* fc_w  = (const float*)d_in[9];
    const float* fc_b  = (const float*)d_in[10];
    float* out = (float*)d_out;

    gru_overlap_kernel<<<GRID, 32>>>(x, w_ih0, b_ih0, w_hh0, b_hh0,
                                     w_ih1, w_hh1, b_ih1, b_hh1,
                                     fc_w, fc_b, out);
}

// round 16
// speedup vs baseline: 2.2870x; 2.2870x over previous
#include <cuda_runtime.h>

// GRU_67714454389230: 2-layer GRU (H=12, IN=18) + fc(12->1), B=4096, T=512.
// Round 16 = Round 8 (measured best, 416.1us) + zero-risk shaves:
//  - gi planes padded by 2 elements -> UNCONDITIONAL t+2 prefetch (no clamp
//    ternary / clamped-index arithmetic in the loop).
// Structure (all measured-best): two kernels; gi0 packed planes (ull rz +
// float n); scan = 1024 single-warp blocks, 2 groups x 2 batches, ALL
// recurrent weights in registers as f32x2, layer-pipelined (layer2@t and
// layer1@t+1 concurrent), combined smem exchange, fc on idle lanes.

static constexpr int IN_DIM = 18;
static constexpr int HID    = 12;
static constexpr int BATCH  = 4096;
static constexpr int SEQ    = 512;
static constexpr size_t NROWS = (size_t)BATCH * SEQ;   // 2,097,152

typedef unsigned long long ull;

// plane layouts, row = b*SEQ + t ; +2 pad elements for unconditional prefetch
__device__ ull   g_gi_rz[HID * NROWS + 2];   // pack(gi_r, gi_z)
__device__ float g_gi_n [HID * NROWS + 2];

// ---------------- helpers ----------------
__device__ __forceinline__ ull ffma2(ull a, ull b, ull c) {
    ull d;
    asm("fma.rn.f32x2 %0, %1, %2, %3;" : "=l"(d) : "l"(a), "l"(b), "l"(c));
    return d;
}
__device__ __forceinline__ float f2sum(ull v) {
    float lo, hi;
    asm("mov.b64 {%0, %1}, %2;" : "=f"(lo), "=f"(hi) : "l"(v));
    return lo + hi;
}
__device__ __forceinline__ ull fpack(float lo, float hi) {
    ull v;
    asm("mov.b64 %0, {%1, %2};" : "=l"(v) : "f"(lo), "f"(hi));
    return v;
}
__device__ __forceinline__ void funpack(ull v, float& lo, float& hi) {
    asm("mov.b64 {%0, %1}, %2;" : "=f"(lo), "=f"(hi) : "l"(v));
}
__device__ __forceinline__ float tanhapx(float x) {
    float y;
    asm("tanh.approx.f32 %0, %1;" : "=f"(y) : "f"(x));
    return y;
}
__device__ __forceinline__ float fast_sig(float x) {
    return fmaf(tanhapx(0.5f * x), 0.5f, 0.5f);
}

// ---------------- kernel 1: gi0 = x @ W_ih0^T + b_ih0 ----------------
static constexpr int GI_ROWS = 512;

__global__ __launch_bounds__(128, 4)
void gi0_kernel(const float* __restrict__ x,
                const float* __restrict__ w_ih0,
                const float* __restrict__ b_ih0)
{
    __shared__ ull   s_xu[GI_ROWS * 11];   // 9 pairs + pad to 11 -> conflict-free
    __shared__ ull   s_w[36][9];
    __shared__ float s_b[36];

    const int tid = threadIdx.x;
    for (int i = tid; i < 36 * 9; i += 128) {
        const int j = i / 9, k = i % 9;
        s_w[j][k] = *(const ull*)(w_ih0 + j * IN_DIM + 2 * k);
    }
    if (tid < 36) s_b[tid] = b_ih0[tid];

    const size_t row0 = (size_t)blockIdx.x * GI_ROWS;
    const float* xg = x + row0 * IN_DIM;
    for (int i = tid; i < GI_ROWS * 9; i += 128) {
        const int r = i / 9, p = i % 9;
        s_xu[r * 11 + p] = *(const ull*)(xg + r * IN_DIM + 2 * p);
    }
    __syncthreads();

    ull xp[4][9];
#pragma unroll
    for (int j = 0; j < 4; ++j) {
        const ull* row = s_xu + (tid + j * 128) * 11;
#pragma unroll
        for (int k = 0; k < 9; ++k) xp[j][k] = row[k];
    }

#pragma unroll
    for (int u = 0; u < HID; ++u) {
        float res[4][3];
#pragma unroll
        for (int g = 0; g < 3; ++g) {
            const int jrow = g * HID + u;
            ull w[9];
#pragma unroll
            for (int k = 0; k < 9; ++k) w[k] = s_w[jrow][k];
            const float b = s_b[jrow];
#pragma unroll
            for (int j = 0; j < 4; ++j) {
                ull acc = fpack(b, 0.0f);
#pragma unroll
                for (int k = 0; k < 9; ++k) acc = ffma2(xp[j][k], w[k], acc);
                res[j][g] = f2sum(acc);
            }
        }
        ull*   prz = g_gi_rz + (size_t)u * NROWS + row0;
        float* pn  = g_gi_n  + (size_t)u * NROWS + row0;
#pragma unroll
        for (int j = 0; j < 4; ++j) {
            prz[tid + j * 128] = fpack(res[j][0], res[j][1]);
            pn [tid + j * 128] = res[j][2];
        }
    }
}

// ---------------- kernel 2: recurrent scan (layer-pipelined) ----------------
// 1024 single-warp blocks: 2 groups of 16 lanes, 2 batches per group.
static constexpr int S_THREADS = 32;
static constexpr int S_GRID    = BATCH / 4;   // 1024 blocks

__global__ __launch_bounds__(S_THREADS, 8)
void gru_scan_kernel(const float* __restrict__ w_hh0, const float* __restrict__ b_hh0,
                     const float* __restrict__ w_ih1, const float* __restrict__ w_hh1,
                     const float* __restrict__ b_ih1, const float* __restrict__ b_hh1,
                     const float* __restrict__ fc_w, const float* __restrict__ fc_b,
                     float* __restrict__ out)
{
    __shared__ __align__(16) float s_h1[2][2][HID];   // [group][batch][unit]
    __shared__ __align__(16) float s_h2[2][2][HID];
    __shared__ float s_fcw[HID];

    const int tid   = threadIdx.x;
    const int grp_l = tid >> 4;
    const int sub   = tid & 15;
    const int u     = (sub < HID) ? sub : HID - 1;
    const int bA    = blockIdx.x * 4 + grp_l * 2;
    const int bB    = bA + 1;

    if (tid < HID) s_fcw[tid] = fc_w[tid];

    // All recurrent weights in registers (f32x2 pairs).
    ull whh0[3][6], wih1[3][6], whh1[3][6];
#pragma unroll
    for (int g = 0; g < 3; ++g) {
        const ull* p0 = (const ull*)(w_hh0 + (g * HID + u) * HID);
        const ull* p1 = (const ull*)(w_ih1 + (g * HID + u) * HID);
        const ull* p2 = (const ull*)(w_hh1 + (g * HID + u) * HID);
#pragma unroll
        for (int i = 0; i < 6; ++i) {
            whh0[g][i] = p0[i]; wih1[g][i] = p1[i]; whh1[g][i] = p2[i];
        }
    }

    const float bh0r = b_hh0[u];
    const float bh0z = b_hh0[HID + u];
    const float bh0n = b_hh0[2 * HID + u];
    const ull pbh0n = fpack(bh0n, 0.0f);
    const ull pb2r  = fpack(b_ih1[u]           + b_hh1[u],          0.0f);
    const ull pb2z  = fpack(b_ih1[HID + u]     + b_hh1[HID + u],    0.0f);
    const ull pb2in = fpack(b_ih1[2 * HID + u], 0.0f);
    const ull pb2hn = fpack(b_hh1[2 * HID + u], 0.0f);
    const float fcb = fc_b[0];

    const ull*   grzA = g_gi_rz + (size_t)u * NROWS + (size_t)bA * SEQ;
    const ull*   grzB = g_gi_rz + (size_t)u * NROWS + (size_t)bB * SEQ;
    const float* gnpA = g_gi_n  + (size_t)u * NROWS + (size_t)bA * SEQ;
    const float* gnpB = g_gi_n  + (size_t)u * NROWS + (size_t)bB * SEQ;

    ull H1A[6], H1B[6], H2A[6], H2B[6];
#pragma unroll
    for (int i = 0; i < 6; ++i) { H1A[i] = H1B[i] = H2A[i] = H2B[i] = 0ull; }
    float hp1A, hp1B, hp2A = 0.0f, hp2B = 0.0f;
    __syncthreads();   // s_fcw visible

    // ---- prologue: h1[0] = GRU1(gi0[0], 0)  (hh contribution = bias only) ----
    {
        float grA, gzA, grB, gzB;
        funpack(grzA[0], grA, gzA);
        funpack(grzB[0], grB, gzB);
        const float gnA0 = gnpA[0], gnB0 = gnpB[0];
        const float rA = fast_sig(grA + bh0r);
        const float rB = fast_sig(grB + bh0r);
        const float zA = fast_sig(gzA + bh0z);
        const float zB = fast_sig(gzB + bh0z);
        const float nA = tanhapx(fmaf(rA, bh0n, gnA0));
        const float nB = tanhapx(fmaf(rB, bh0n, gnB0));
        hp1A = nA - zA * nA;
        hp1B = nB - zB * nB;
        if (sub < HID) { s_h1[grp_l][0][u] = hp1A; s_h1[grp_l][1][u] = hp1B; }
        __syncwarp();
        const ulonglong2* pa = (const ulonglong2*)s_h1[grp_l][0];
        const ulonglong2* pb = (const ulonglong2*)s_h1[grp_l][1];
        const ulonglong2 a0 = pa[0], a1 = pa[1], a2 = pa[2];
        const ulonglong2 b0 = pb[0], b1 = pb[1], b2 = pb[2];
        H1A[0] = a0.x; H1A[1] = a0.y; H1A[2] = a1.x;
        H1A[3] = a1.y; H1A[4] = a2.x; H1A[5] = a2.y;
        H1B[0] = b0.x; H1B[1] = b0.y; H1B[2] = b1.x;
        H1B[3] = b1.y; H1B[4] = b2.x; H1B[5] = b2.y;
    }

    // gi for t+1=1 (consumed by layer1 inside iteration t=0)
    ull   rzA = grzA[1], rzB = grzB[1];
    float gnA = gnpA[1], gnB = gnpB[1];

#pragma unroll 1
    for (int t = 0; t < SEQ; ++t) {
        // UNCONDITIONAL prefetch (planes padded by 2 elements; overreads land
        // in pad or the next batch's region and are never consumed).
        const ull   rzA_n = grzA[t + 2];
        const ull   rzB_n = grzB[t + 2];
        const float gnA_n = gnpA[t + 2];
        const float gnB_n = gnpB[t + 2];

        // ======== layer 2 for step t (uses H1 = h1[t], H2 = h2[t-1]) ========
        ull prA = pb2r, pzA = pb2z, pnA = pb2hn, piA = pb2in;
        ull prB = pb2r, pzB = pb2z, pnB = pb2hn, piB = pb2in;
        // ======== layer 1 for step t+1 (uses gi(t+1), H1 = h1[t]) ========
        float grA, gzA2, grB, gzB2;
        funpack(rzA, grA, gzA2);
        funpack(rzB, grB, gzB2);
        ull qrA = fpack(grA, bh0r), qzA = fpack(gzA2, bh0z), qnA = pbh0n;
        ull qrB = fpack(grB, bh0r), qzB = fpack(gzB2, bh0z), qnB = pbh0n;

#pragma unroll
        for (int i = 0; i < 6; ++i) {
            prA = ffma2(H2A[i], whh1[0][i], prA); prB = ffma2(H2B[i], whh1[0][i], prB);
            pzA = ffma2(H2A[i], whh1[1][i], pzA); pzB = ffma2(H2B[i], whh1[1][i], pzB);
            pnA = ffma2(H2A[i], whh1[2][i], pnA); pnB = ffma2(H2B[i], whh1[2][i], pnB);
            prA = ffma2(H1A[i], wih1[0][i], prA); prB = ffma2(H1B[i], wih1[0][i], prB);
            pzA = ffma2(H1A[i], wih1[1][i], pzA); pzB = ffma2(H1B[i], wih1[1][i], pzB);
            piA = ffma2(H1A[i], wih1[2][i], piA); piB = ffma2(H1B[i], wih1[2][i], piB);
            qrA = ffma2(H1A[i], whh0[0][i], qrA); qrB = ffma2(H1B[i], whh0[0][i], qrB);
            qzA = ffma2(H1A[i], whh0[1][i], qzA); qzB = ffma2(H1B[i], whh0[1][i], qzB);
            qnA = ffma2(H1A[i], whh0[2][i], qnA); qnB = ffma2(H1B[i], whh0[2][i], qnB);
        }

        // layer2 activations -> h2[t]
        const float r2A = fast_sig(f2sum(prA));
        const float r2B = fast_sig(f2sum(prB));
        const float z2A = fast_sig(f2sum(pzA));
        const float z2B = fast_sig(f2sum(pzB));
        const float n2A = tanhapx(fmaf(r2A, f2sum(pnA), f2sum(piA)));
        const float n2B = tanhapx(fmaf(r2B, f2sum(pnB), f2sum(piB)));
        const float hn2A = fmaf(z2A, hp2A - n2A, n2A);
        const float hn2B = fmaf(z2B, hp2B - n2B, n2B);
        hp2A = hn2A; hp2B = hn2B;

        // layer1 activations -> h1[t+1]
        const float r1A = fast_sig(f2sum(qrA));
        const float r1B = fast_sig(f2sum(qrB));
        const float z1A = fast_sig(f2sum(qzA));
        const float z1B = fast_sig(f2sum(qzB));
        const float n1A = tanhapx(fmaf(r1A, f2sum(qnA), gnA));
        const float n1B = tanhapx(fmaf(r1B, f2sum(qnB), gnB));
        const float hn1A = fmaf(z1A, hp1A - n1A, n1A);
        const float hn1B = fmaf(z1B, hp1B - n1B, n1B);
        hp1A = hn1A; hp1B = hn1B;

        // ======== combined exchange ========
        if (sub < HID) {
            s_h1[grp_l][0][u] = hn1A; s_h1[grp_l][1][u] = hn1B;
            s_h2[grp_l][0][u] = hn2A; s_h2[grp_l][1][u] = hn2B;
        }
        __syncwarp();
        {
            const ulonglong2* pa = (const ulonglong2*)s_h1[grp_l][0];
            const ulonglong2* pb = (const ulonglong2*)s_h1[grp_l][1];
            const ulonglong2 a0 = pa[0], a1 = pa[1], a2 = pa[2];
            const ulonglong2 b0 = pb[0], b1 = pb[1], b2 = pb[2];
            H1A[0] = a0.x; H1A[1] = a0.y; H1A[2] = a1.x;
            H1A[3] = a1.y; H1A[4] = a2.x; H1A[5] = a2.y;
            H1B[0] = b0.x; H1B[1] = b0.y; H1B[2] = b1.x;
            H1B[3] = b1.y; H1B[4] = b2.x; H1B[5] = b2.y;
        }
        {
            const ulonglong2* pa = (const ulonglong2*)s_h2[grp_l][0];
            const ulonglong2* pb = (const ulonglong2*)s_h2[grp_l][1];
            const ulonglong2 a0 = pa[0], a1 = pa[1], a2 = pa[2];
            const ulonglong2 b0 = pb[0], b1 = pb[1], b2 = pb[2];
            H2A[0] = a0.x; H2A[1] = a0.y; H2A[2] = a1.x;
            H2A[3] = a1.y; H2A[4] = a2.x; H2A[5] = a2.y;
            H2B[0] = b0.x; H2B[1] = b0.y; H2B[2] = b1.x;
            H2B[3] = b1.y; H2B[4] = b2.x; H2B[5] = b2.y;
        }

        // ======== fc(h2[t]) on idle lanes 12 (A) / 13 (B) ========
        if (sub >= 12 && sub < 14) {
            const ull* hh = (sub == 12) ? H2A : H2B;
            ull acc = fpack(fcb, 0.0f);
#pragma unroll
            for (int i = 0; i < 6; ++i)
                acc = ffma2(hh[i], *(const ull*)&s_fcw[2 * i], acc);
            out[(size_t)((sub == 12) ? bA : bB) * SEQ + t] = f2sum(acc);
        }

        rzA = rzA_n; rzB = rzB_n; gnA = gnA_n; gnB = gnB_n;
    }
}

extern "C" void kernel_launch(void* const* d_in, const int* in_sizes, int n_in,
                              void* d_out, int out_size) {
    const float* x     = (const float*)d_in[0];
    const float* w_ih0 = (const float*)d_in[1];
    const float* w_hh0 = (const float*)d_in[2];
    const float* b_ih0 = (const float*)d_in[3];
    const float* b_hh0 = (const float*)d_in[4];
    const float* w_ih1 = (const float*)d_in[5];
    const float* w_hh1 = (const float*)d_in[6];
    const float* b_ih1 = (const float*)d_in[7];
    const float* b_hh1 = (const float*)d_in[8];
    const float* fc_w  = (const float*)d_in[9];
    const float* fc_b  = (const float*)d_in[10];
    float* out = (float*)d_out;

    gi0_kernel<<<(int)(NROWS / GI_ROWS), 128>>>(x, w_ih0, b_ih0);
    gru_scan_kernel<<<S_GRID, S_THREADS>>>(w_hh0, b_hh0, w_ih1, w_hh1,
                                           b_ih1, b_hh1, fc_w, fc_b, out);
}